// round 7
// baseline (speedup 1.0000x reference)
#include <cuda_runtime.h>
#include <cuda_fp16.h>
#include <stdint.h>

// AllZeroDigitalFilter via fp16 tensor cores (mma.sync.m16n8k16, fp32 accum).
// Per segment n: out[p] = y0[p] + (p/80)*y1[p], where
//   [y0 y1] = Xwin[80 x 256] * [h0 d]  (Toeplitz A: A[p,k] = x[n*80 + p - k])
// Precision: hi/lo fp16 split of x and coefficients, 3-MMA compensated scheme.
// One warp per segment; 8 segments per block; grid (100, 8).

#define NB   800
#define PP   80
#define TAPS 256
#define SEG  8
#define TT   (NB * PP)
#define NTH  256
#define APAD 464   // phase-array stride (half2 units); %32==16 -> E/O bank-disjoint

__device__ __forceinline__ void mma16816(float* c,
    uint32_t a0, uint32_t a1, uint32_t a2, uint32_t a3,
    uint32_t b0, uint32_t b1)
{
    asm volatile(
        "mma.sync.aligned.m16n8k16.row.col.f32.f16.f16.f32 "
        "{%0,%1,%2,%3}, {%4,%5,%6,%7}, {%8,%9}, {%0,%1,%2,%3};"
        : "+f"(c[0]), "+f"(c[1]), "+f"(c[2]), "+f"(c[3])
        : "r"(a0), "r"(a1), "r"(a2), "r"(a3), "r"(b0), "r"(b1));
}

__global__ __launch_bounds__(NTH)
void azdf_mma(const float* __restrict__ x,
              const float* __restrict__ h,
              float* __restrict__ out)
{
    __shared__ float   swf[904];                    // staged reversed x window (float)
    __shared__ __half2 sAh[2][APAD];                // [phase E/O][v] hi pairs
    __shared__ __half2 sAl[2][APAD];                // lo pairs
    __shared__ __half  sCoef[2][2][SEG][TAPS];      // [filter 0=h0,1=d][hi/lo][seg][k]
    __shared__ __half  sZero[16];

    const int tid = threadIdx.x;
    const int b   = blockIdx.y;
    const int n0  = blockIdx.x * SEG;

    if (tid < 16) sZero[tid] = __float2half(0.0f);

    // ---- stage reversed window: swf[i] = x[b, n0*80 + 640 - i], OOB -> 0
    {
        const float* xb = x + (size_t)b * TT;
        const int gb = n0 * PP + 640;
        for (int i = tid; i < 904; i += NTH) {
            int gt = gb - i;
            swf[i] = (gt >= 0 && gt < TT) ? xb[gt] : 0.0f;
        }
    }
    // ---- stage coefficients (hi/lo split of h0 and d = h1 - h0)
    {
        for (int idx = tid; idx < SEG * TAPS; idx += NTH) {
            int s = idx >> 8, k = idx & 255;
            int n  = n0 + s;
            int nn = (n + 1 < NB) ? (n + 1) : (NB - 1);
            float a = h[((size_t)b * NB + n)  * TAPS + k];
            float c = h[((size_t)b * NB + nn) * TAPS + k];
            float d = c - a;
            __half ah = __float2half_rn(a);
            __half al = __float2half_rn(a - __half2float(ah));
            __half dh = __float2half_rn(d);
            __half dl = __float2half_rn(d - __half2float(dh));
            sCoef[0][0][s][k] = ah; sCoef[0][1][s][k] = al;
            sCoef[1][0][s][k] = dh; sCoef[1][1][s][k] = dl;
        }
    }
    __syncthreads();

    // ---- build parity-split half2 pair arrays of the reversed window
    // E[v] = {w[2v], w[2v+1]},  O[v] = {w[2v+1], w[2v+2]}  (w = swf, hi & lo)
    for (int v = tid; v < 450; v += NTH) {
        float f0 = swf[2*v], f1 = swf[2*v+1], f2 = swf[2*v+2];
        __half h0 = __float2half_rn(f0), h1 = __float2half_rn(f1), h2 = __float2half_rn(f2);
        __half l0 = __float2half_rn(f0 - __half2float(h0));
        __half l1 = __float2half_rn(f1 - __half2float(h1));
        __half l2 = __float2half_rn(f2 - __half2float(h2));
        sAh[0][v] = __halves2half2(h0, h1);
        sAh[1][v] = __halves2half2(h1, h2);
        sAl[0][v] = __halves2half2(l0, l1);
        sAl[1][v] = __halves2half2(l1, l2);
    }
    __syncthreads();

    // ---- compute: one warp per segment
    const int s    = tid >> 5;
    const int lane = tid & 31;
    const int g    = lane >> 2;     // fragment group row / B column n
    const int tg   = lane & 3;      // thread-in-group

    // A pair base index: u00 = 640 - 80s - g + 2tg; parity(u00) == parity(g)
    const int u00 = 640 - PP * s - g + 2 * tg;
    const int V0  = (u00 - (g & 1)) >> 1;
    const uint32_t* pAh = reinterpret_cast<const uint32_t*>(&sAh[g & 1][0]);
    const uint32_t* pAl = reinterpret_cast<const uint32_t*>(&sAl[g & 1][0]);

    // B pointers: n=0 -> h0, n=1 -> d, n>=2 -> zeros (stride 0)
    const __half* pBh;
    const __half* pBl;
    int bstride;
    if (g < 2) {
        pBh = &sCoef[g][0][s][2 * tg];
        pBl = &sCoef[g][1][s][2 * tg];
        bstride = 16;
    } else {
        pBh = sZero; pBl = sZero; bstride = 0;
    }

    float acc[5][4] = {};

    #pragma unroll
    for (int c = 0; c < 4; c++) {                  // ks chunks of 4
        uint32_t b0h[4], b1h[4], b0l[4], b1l[4];
        #pragma unroll
        for (int i = 0; i < 4; i++) {
            int ks = 4 * c + i;
            b0h[i] = *reinterpret_cast<const uint32_t*>(pBh + ks * bstride);
            b1h[i] = *reinterpret_cast<const uint32_t*>(pBh + ks * bstride + 8);
            b0l[i] = *reinterpret_cast<const uint32_t*>(pBl + ks * bstride);
            b1l[i] = *reinterpret_cast<const uint32_t*>(pBl + ks * bstride + 8);
        }
        // Toeplitz: A tile depends only on d = i - m  (vv = V0 + 32c + 8d)
        #pragma unroll
        for (int d = -4; d <= 3; d++) {
            const int vv = V0 + 32 * c + 8 * d;
            uint32_t a0 = pAh[vv], a1 = pAh[vv - 4], a2 = pAh[vv + 4];
            uint32_t l0 = pAl[vv], l1 = pAl[vv - 4], l2 = pAl[vv + 4];
            #pragma unroll
            for (int m = 0; m < 5; m++) {
                const int i = m + d;
                if (i < 0 || i > 3) continue;       // compile-time pruned
                mma16816(acc[m], a0, a1, a2, a0, b0h[i], b1h[i]);  // Ahi*Bhi
                mma16816(acc[m], l0, l1, l2, l0, b0h[i], b1h[i]);  // Alo*Bhi
                mma16816(acc[m], a0, a1, a2, a0, b0l[i], b1l[i]);  // Ahi*Blo
            }
        }
    }

    // ---- epilogue: lanes with tg==0 hold C cols 0 (y0) and 1 (y1)
    if (tg == 0) {
        const float inv = 1.0f / (float)PP;
        float* ob = out + (size_t)b * TT + (size_t)(n0 + s) * PP;
        #pragma unroll
        for (int m = 0; m < 5; m++) {
            int p = 16 * m + g;
            ob[p]     = acc[m][0] + (float)p       * inv * acc[m][1];
            ob[p + 8] = acc[m][2] + (float)(p + 8) * inv * acc[m][3];
        }
    }
}

extern "C" void kernel_launch(void* const* d_in, const int* in_sizes, int n_in,
                              void* d_out, int out_size)
{
    const float* x = (const float*)d_in[0];
    const float* h = (const float*)d_in[1];
    float* out = (float*)d_out;
    (void)in_sizes; (void)n_in; (void)out_size;

    dim3 grid(NB / SEG, 8);   // 100 x 8
    azdf_mma<<<grid, NTH>>>(x, h, out);
}

// round 8
// speedup vs baseline: 1.0236x; 1.0236x over previous
#include <cuda_runtime.h>
#include <cuda_fp16.h>
#include <stdint.h>

// AllZeroDigitalFilter via fp16 tensor cores (mma.sync.m16n8k16, fp32 accum).
// Per segment n: out[p] = y0[p] + (p/80)*y1[p],
//   [y0 y1] = Xwin[80 x 256] * [h0 d]   (Toeplitz A: A[p,k] = x[n*80 + p - k])
// Compensated fp16: B columns = [h0_hi, d_hi, h0_lo, d_lo, 0,0,0,0];
// two MMAs per tile (A_hi*B, A_lo*B) produce all 4 cross terms:
//   y = (Ahi+Alo)*(Bhi+Blo), combined via column sum (epilogue shuffles).
// One warp per segment; 8 segments per block; grid (100, 8).

#define NB   800
#define PP   80
#define TAPS 256
#define SEG  8
#define TT   (NB * PP)
#define NTH  256
#define APAD 464   // phase-array stride (half2 units)

__device__ __forceinline__ void mma16816(float* c,
    uint32_t a0, uint32_t a1, uint32_t a2, uint32_t a3,
    uint32_t b0, uint32_t b1)
{
    asm volatile(
        "mma.sync.aligned.m16n8k16.row.col.f32.f16.f16.f32 "
        "{%0,%1,%2,%3}, {%4,%5,%6,%7}, {%8,%9}, {%0,%1,%2,%3};"
        : "+f"(c[0]), "+f"(c[1]), "+f"(c[2]), "+f"(c[3])
        : "r"(a0), "r"(a1), "r"(a2), "r"(a3), "r"(b0), "r"(b1));
}

__global__ __launch_bounds__(NTH)
void azdf_mma(const float* __restrict__ x,
              const float* __restrict__ h,
              float* __restrict__ out)
{
    __shared__ float   swf[904];                    // staged reversed x window
    __shared__ __half2 sAh[2][APAD];                // [phase E/O] hi pairs
    __shared__ __half2 sAl[2][APAD];                // lo pairs
    __shared__ __half  sCoef[2][2][SEG][TAPS];      // [filt 0=h0,1=d][0=hi,1=lo][seg][k]
    __shared__ __half  sZero[16];

    const int tid = threadIdx.x;
    const int b   = blockIdx.y;
    const int n0  = blockIdx.x * SEG;

    if (tid < 16) sZero[tid] = __float2half(0.0f);

    // ---- stage reversed window: swf[i] = x[b, n0*80 + 640 - i], OOB -> 0
    {
        const float* xb = x + (size_t)b * TT;
        const int gb = n0 * PP + 640;
        for (int i = tid; i < 904; i += NTH) {
            int gt = gb - i;
            swf[i] = (gt >= 0 && gt < TT) ? xb[gt] : 0.0f;
        }
    }
    // ---- stage coefficients (hi/lo split of h0 and d = h1 - h0)
    for (int idx = tid; idx < SEG * TAPS; idx += NTH) {
        int s = idx >> 8, k = idx & 255;
        int n  = n0 + s;
        int nn = (n + 1 < NB) ? (n + 1) : (NB - 1);
        float a = h[((size_t)b * NB + n)  * TAPS + k];
        float c = h[((size_t)b * NB + nn) * TAPS + k];
        float d = c - a;
        __half ah = __float2half_rn(a);
        __half al = __float2half_rn(a - __half2float(ah));
        __half dh = __float2half_rn(d);
        __half dl = __float2half_rn(d - __half2float(dh));
        sCoef[0][0][s][k] = ah; sCoef[0][1][s][k] = al;
        sCoef[1][0][s][k] = dh; sCoef[1][1][s][k] = dl;
    }
    __syncthreads();

    // ---- parity-split half2 pair arrays of the reversed window
    // E[v] = {w[2v], w[2v+1]},  O[v] = {w[2v+1], w[2v+2]}  (hi & lo parts)
    for (int v = tid; v < 450; v += NTH) {
        float f0 = swf[2*v], f1 = swf[2*v+1], f2 = swf[2*v+2];
        __half h0 = __float2half_rn(f0), h1 = __float2half_rn(f1), h2 = __float2half_rn(f2);
        __half l0 = __float2half_rn(f0 - __half2float(h0));
        __half l1 = __float2half_rn(f1 - __half2float(h1));
        __half l2 = __float2half_rn(f2 - __half2float(h2));
        sAh[0][v] = __halves2half2(h0, h1);
        sAh[1][v] = __halves2half2(h1, h2);
        sAl[0][v] = __halves2half2(l0, l1);
        sAl[1][v] = __halves2half2(l1, l2);
    }
    __syncthreads();

    // ---- compute: one warp per segment
    const int s    = tid >> 5;
    const int lane = tid & 31;
    const int g    = lane >> 2;     // fragment row group / B column
    const int tg   = lane & 3;

    const int u00 = 640 - PP * s - g + 2 * tg;
    const int V0  = (u00 - (g & 1)) >> 1;
    const uint32_t* pAh = reinterpret_cast<const uint32_t*>(&sAh[g & 1][0]);
    const uint32_t* pAl = reinterpret_cast<const uint32_t*>(&sAl[g & 1][0]);

    // B columns: 0=h0_hi, 1=d_hi, 2=h0_lo, 3=d_lo, 4..7=zero
    const __half* pB;
    int bstride;
    if      (g == 0) { pB = &sCoef[0][0][s][2 * tg]; bstride = 16; }
    else if (g == 1) { pB = &sCoef[1][0][s][2 * tg]; bstride = 16; }
    else if (g == 2) { pB = &sCoef[0][1][s][2 * tg]; bstride = 16; }
    else if (g == 3) { pB = &sCoef[1][1][s][2 * tg]; bstride = 16; }
    else             { pB = sZero;                   bstride = 0;  }

    float accH[5][4] = {};   // A_hi * B
    float accL[5][4] = {};   // A_lo * B

    #pragma unroll
    for (int c = 0; c < 4; c++) {                  // ks chunks of 4
        uint32_t b0[4], b1[4];
        #pragma unroll
        for (int i = 0; i < 4; i++) {
            int ks = 4 * c + i;
            b0[i] = *reinterpret_cast<const uint32_t*>(pB + ks * bstride);
            b1[i] = *reinterpret_cast<const uint32_t*>(pB + ks * bstride + 8);
        }
        // Toeplitz: A tile depends only on d = i - m  (vv = V0 + 32c + 8d)
        #pragma unroll
        for (int d = -4; d <= 3; d++) {
            const int vv = V0 + 32 * c + 8 * d;
            uint32_t a0 = pAh[vv], a1 = pAh[vv - 4], a2 = pAh[vv + 4];
            uint32_t l0 = pAl[vv], l1 = pAl[vv - 4], l2 = pAl[vv + 4];
            #pragma unroll
            for (int m = 0; m < 5; m++) {
                const int i = m + d;
                if (i < 0 || i > 3) continue;       // compile-time pruned
                mma16816(accH[m], a0, a1, a2, a0, b0[i], b1[i]);
                mma16816(accL[m], l0, l1, l2, l0, b0[i], b1[i]);
            }
        }
    }

    // ---- epilogue: per-thread hi+lo, then column-pair combine via shuffle.
    // Thread (g,tg) holds C rows {g, g+8}, cols {2tg, 2tg+1}.
    // y0 = col0 + col2, y1 = col1 + col3  ->  tg0 (+) tg1 via shfl_down 1.
    const float inv = 1.0f / (float)PP;
    float* ob = out + (size_t)b * TT + (size_t)(n0 + s) * PP;
    #pragma unroll
    for (int m = 0; m < 5; m++) {
        float t0 = accH[m][0] + accL[m][0];
        float t1 = accH[m][1] + accL[m][1];
        float t2 = accH[m][2] + accL[m][2];
        float t3 = accH[m][3] + accL[m][3];
        float s0 = t0 + __shfl_down_sync(0xffffffffu, t0, 1);  // y0 row g
        float s1 = t1 + __shfl_down_sync(0xffffffffu, t1, 1);  // y1 row g
        float s2 = t2 + __shfl_down_sync(0xffffffffu, t2, 1);  // y0 row g+8
        float s3 = t3 + __shfl_down_sync(0xffffffffu, t3, 1);  // y1 row g+8
        if (tg == 0) {
            int p = 16 * m + g;
            ob[p]     = s0 + (float)p       * inv * s1;
            ob[p + 8] = s2 + (float)(p + 8) * inv * s3;
        }
    }
}

extern "C" void kernel_launch(void* const* d_in, const int* in_sizes, int n_in,
                              void* d_out, int out_size)
{
    const float* x = (const float*)d_in[0];
    const float* h = (const float*)d_in[1];
    float* out = (float*)d_out;
    (void)in_sizes; (void)n_in; (void)out_size;

    dim3 grid(NB / SEG, 8);   // 100 x 8
    azdf_mma<<<grid, NTH>>>(x, h, out);
}